// round 1
// baseline (speedup 1.0000x reference)
#include <cuda_runtime.h>
#include <cstdint>

#define NE 8
#define TOPK 2
#define DD 2048
#define MM 7168
#define NTOK 4096
#define NPAIR 8192
#define PADROWS 9216
#define MAXTILES 72
#define BM 128
#define BN 64
#define BK 16
#define AS_LD 20
#define BS_LD 72

// ---- scratch (device globals; no runtime allocation allowed) ----
__device__ float g_h[(size_t)PADROWS * MM];       // hidden after silu*w3 gate
__device__ float g_outs[(size_t)PADROWS * DD];    // per-pair expert outputs (sorted order)
__device__ int   g_row_token[PADROWS];
__device__ int   g_pair_row[NPAIR];
__device__ int   g_tk_idx[NTOK * 2];
__device__ float g_tk_w[NTOK * 2];
__device__ int   g_counts[NE];
__device__ int   g_cursor[NE];
__device__ int   g_pad_off[NE + 1];
__device__ int   g_tile_expert[MAXTILES];
__device__ int   g_tile_row[MAXTILES];

// ---- helpers ----
__device__ __forceinline__ uint32_t f2tf(float f) {
    uint32_t u;
    asm("cvt.rna.tf32.f32 %0, %1;" : "=r"(u) : "f"(f));
    return u;
}

__device__ __forceinline__ void mma_tf32(float c[4],
                                         uint32_t a0, uint32_t a1, uint32_t a2, uint32_t a3,
                                         uint32_t b0, uint32_t b1) {
    asm volatile(
        "mma.sync.aligned.m16n8k8.row.col.f32.tf32.tf32.f32 "
        "{%0,%1,%2,%3},{%4,%5,%6,%7},{%8,%9},{%0,%1,%2,%3};\n"
        : "+f"(c[0]), "+f"(c[1]), "+f"(c[2]), "+f"(c[3])
        : "r"(a0), "r"(a1), "r"(a2), "r"(a3), "r"(b0), "r"(b1));
}

__device__ __forceinline__ float silu_f(float v) {
    return v / (1.0f + __expf(-v));
}

// ---- init: zero counters, default row->token mapping (padding rows read x[0]) ----
__global__ void init_kernel() {
    int i = blockIdx.x * 256 + threadIdx.x;
    if (i < PADROWS) g_row_token[i] = 0;
    if (i < NE) { g_counts[i] = 0; g_cursor[i] = 0; }
}

// ---- router: one block per token ----
__global__ __launch_bounds__(256) void router_kernel(const float* __restrict__ x,
                                                     const float* __restrict__ gw) {
    int t = blockIdx.x;
    const float* xr = x + (size_t)t * DD;
    float acc[NE];
#pragma unroll
    for (int e = 0; e < NE; e++) acc[e] = 0.0f;
    for (int k = threadIdx.x; k < DD; k += 256) {
        float xv = xr[k];
        float4 g0 = *(const float4*)(gw + (size_t)k * NE);
        float4 g1 = *(const float4*)(gw + (size_t)k * NE + 4);
        acc[0] += xv * g0.x; acc[1] += xv * g0.y;
        acc[2] += xv * g0.z; acc[3] += xv * g0.w;
        acc[4] += xv * g1.x; acc[5] += xv * g1.y;
        acc[6] += xv * g1.z; acc[7] += xv * g1.w;
    }
#pragma unroll
    for (int e = 0; e < NE; e++)
#pragma unroll
        for (int o = 16; o > 0; o >>= 1)
            acc[e] += __shfl_down_sync(0xffffffffu, acc[e], o);
    __shared__ float s[8][NE];
    int warp = threadIdx.x >> 5, lane = threadIdx.x & 31;
    if (lane == 0)
#pragma unroll
        for (int e = 0; e < NE; e++) s[warp][e] = acc[e];
    __syncthreads();
    if (threadIdx.x == 0) {
        float lg[NE];
#pragma unroll
        for (int e = 0; e < NE; e++) {
            float v = 0.0f;
#pragma unroll
            for (int w = 0; w < 8; w++) v += s[w][e];
            lg[e] = v;
        }
        float mx = lg[0];
#pragma unroll
        for (int e = 1; e < NE; e++) mx = fmaxf(mx, lg[e]);
        float p[NE];
#pragma unroll
        for (int e = 0; e < NE; e++) p[e] = expf(lg[e] - mx);
        // top-2 (ties -> lower index, matching jax top_k)
        int i1 = 0;
#pragma unroll
        for (int e = 1; e < NE; e++) if (p[e] > p[i1]) i1 = e;
        int i2 = -1;
#pragma unroll
        for (int e = 0; e < NE; e++)
            if (e != i1 && (i2 < 0 || p[e] > p[i2])) i2 = e;
        float denom = p[i1] + p[i2];
        g_tk_idx[2 * t] = i1; g_tk_idx[2 * t + 1] = i2;
        g_tk_w[2 * t] = p[i1] / denom;
        g_tk_w[2 * t + 1] = p[i2] / denom;
        atomicAdd(&g_counts[i1], 1);
        atomicAdd(&g_counts[i2], 1);
    }
}

// ---- scan: padded offsets + tile table (single thread, tiny) ----
__global__ void scan_kernel() {
    if (blockIdx.x == 0 && threadIdx.x == 0) {
        int off = 0, tile = 0;
        for (int e = 0; e < NE; e++) {
            g_pad_off[e] = off;
            int c = g_counts[e];
            int nt = (c + BM - 1) >> 7;
            for (int i = 0; i < nt; i++) {
                g_tile_expert[tile] = e;
                g_tile_row[tile] = off + (i << 7);
                tile++;
            }
            off += nt << 7;
        }
        g_pad_off[NE] = off;
        for (; tile < MAXTILES; tile++) g_tile_expert[tile] = -1;
    }
}

// ---- scatter pairs into padded sorted order ----
__global__ void scatter_kernel() {
    int r = blockIdx.x * 256 + threadIdx.x;
    if (r >= NPAIR) return;
    int e = g_tk_idx[r];
    int p = g_pad_off[e] + atomicAdd(&g_cursor[e], 1);
    g_row_token[p] = r >> 1;
    g_pair_row[r] = p;
}

// ---- fused GEMM1/GEMM3 + silu gate: h = silu(x@w1) * (x@w3) ----
__global__ __launch_bounds__(256) void gemm13_kernel(const float* __restrict__ x,
                                                     const float* __restrict__ w1,
                                                     const float* __restrict__ w3) {
    __shared__ uint32_t As[BM * AS_LD];
    __shared__ uint32_t B1s[BK * BS_LD];
    __shared__ uint32_t B3s[BK * BS_LD];
    __shared__ int toks[BM];

    int e = g_tile_expert[blockIdx.y];
    if (e < 0) return;
    int row0 = g_tile_row[blockIdx.y];
    int n0 = blockIdx.x * BN;
    int tid = threadIdx.x;
    if (tid < BM) toks[tid] = g_row_token[row0 + tid];
    const float* W1 = w1 + (size_t)e * DD * MM;
    const float* W3 = w3 + (size_t)e * DD * MM;

    int warp = tid >> 5, lane = tid & 31;
    int wm = (warp & 1) * 64, wn = (warp >> 1) * 16;
    int gr = lane >> 2, tg = lane & 3;

    float acc1[4][2][4], acc3[4][2][4];
#pragma unroll
    for (int mi = 0; mi < 4; mi++)
#pragma unroll
        for (int ni = 0; ni < 2; ni++)
#pragma unroll
            for (int j = 0; j < 4; j++) { acc1[mi][ni][j] = 0.f; acc3[mi][ni][j] = 0.f; }
    __syncthreads();

    for (int k0 = 0; k0 < DD; k0 += BK) {
        // A tile: gathered token rows, RNA->tf32
#pragma unroll
        for (int i = 0; i < 2; i++) {
            int q = tid + i * 256;
            int row = q >> 2, c4 = q & 3;
            float4 v = *(const float4*)(x + (size_t)toks[row] * DD + k0 + c4 * 4);
            uint32_t* d = &As[row * AS_LD + c4 * 4];
            d[0] = f2tf(v.x); d[1] = f2tf(v.y); d[2] = f2tf(v.z); d[3] = f2tf(v.w);
        }
        // B tiles (w1 and w3)
        {
            int row = tid >> 4, c4 = tid & 15;
            size_t go = (size_t)(k0 + row) * MM + n0 + c4 * 4;
            float4 v1 = *(const float4*)(W1 + go);
            float4 v3 = *(const float4*)(W3 + go);
            uint32_t* d1 = &B1s[row * BS_LD + c4 * 4];
            d1[0] = f2tf(v1.x); d1[1] = f2tf(v1.y); d1[2] = f2tf(v1.z); d1[3] = f2tf(v1.w);
            uint32_t* d3 = &B3s[row * BS_LD + c4 * 4];
            d3[0] = f2tf(v3.x); d3[1] = f2tf(v3.y); d3[2] = f2tf(v3.z); d3[3] = f2tf(v3.w);
        }
        __syncthreads();
#pragma unroll
        for (int kk = 0; kk < BK; kk += 8) {
            uint32_t af[4][4];
#pragma unroll
            for (int mi = 0; mi < 4; mi++) {
                int r = wm + mi * 16 + gr;
                af[mi][0] = As[r * AS_LD + kk + tg];
                af[mi][1] = As[(r + 8) * AS_LD + kk + tg];
                af[mi][2] = As[r * AS_LD + kk + tg + 4];
                af[mi][3] = As[(r + 8) * AS_LD + kk + tg + 4];
            }
#pragma unroll
            for (int ni = 0; ni < 2; ni++) {
                int n = wn + ni * 8 + gr;
                uint32_t b10 = B1s[(kk + tg) * BS_LD + n];
                uint32_t b11 = B1s[(kk + tg + 4) * BS_LD + n];
                uint32_t b30 = B3s[(kk + tg) * BS_LD + n];
                uint32_t b31 = B3s[(kk + tg + 4) * BS_LD + n];
#pragma unroll
                for (int mi = 0; mi < 4; mi++) {
                    mma_tf32(acc1[mi][ni], af[mi][0], af[mi][1], af[mi][2], af[mi][3], b10, b11);
                    mma_tf32(acc3[mi][ni], af[mi][0], af[mi][1], af[mi][2], af[mi][3], b30, b31);
                }
            }
        }
        __syncthreads();
    }
    // epilogue: silu(h1)*h3
#pragma unroll
    for (int mi = 0; mi < 4; mi++)
#pragma unroll
        for (int ni = 0; ni < 2; ni++) {
            int ra = row0 + wm + mi * 16 + gr;
            int ca = n0 + wn + ni * 8 + 2 * tg;
            float* a1 = acc1[mi][ni];
            float* a3 = acc3[mi][ni];
            float2 lo = make_float2(silu_f(a1[0]) * a3[0], silu_f(a1[1]) * a3[1]);
            float2 hi = make_float2(silu_f(a1[2]) * a3[2], silu_f(a1[3]) * a3[3]);
            *(float2*)&g_h[(size_t)ra * MM + ca] = lo;
            *(float2*)&g_h[(size_t)(ra + 8) * MM + ca] = hi;
        }
}

// ---- GEMM2: out_sorted = h @ w2 ----
__global__ __launch_bounds__(256) void gemm2_kernel(const float* __restrict__ w2) {
    __shared__ uint32_t As[BM * AS_LD];
    __shared__ uint32_t Bs[BK * BS_LD];

    int e = g_tile_expert[blockIdx.y];
    if (e < 0) return;
    int row0 = g_tile_row[blockIdx.y];
    int n0 = blockIdx.x * BN;
    int tid = threadIdx.x;
    const float* W2 = w2 + (size_t)e * MM * DD;

    int warp = tid >> 5, lane = tid & 31;
    int wm = (warp & 1) * 64, wn = (warp >> 1) * 16;
    int gr = lane >> 2, tg = lane & 3;

    float acc[4][2][4];
#pragma unroll
    for (int mi = 0; mi < 4; mi++)
#pragma unroll
        for (int ni = 0; ni < 2; ni++)
#pragma unroll
            for (int j = 0; j < 4; j++) acc[mi][ni][j] = 0.f;

    for (int k0 = 0; k0 < MM; k0 += BK) {
#pragma unroll
        for (int i = 0; i < 2; i++) {
            int q = tid + i * 256;
            int row = q >> 2, c4 = q & 3;
            float4 v = *(const float4*)(g_h + (size_t)(row0 + row) * MM + k0 + c4 * 4);
            uint32_t* d = &As[row * AS_LD + c4 * 4];
            d[0] = f2tf(v.x); d[1] = f2tf(v.y); d[2] = f2tf(v.z); d[3] = f2tf(v.w);
        }
        {
            int row = tid >> 4, c4 = tid & 15;
            float4 v = *(const float4*)(W2 + (size_t)(k0 + row) * DD + n0 + c4 * 4);
            uint32_t* d = &Bs[row * BS_LD + c4 * 4];
            d[0] = f2tf(v.x); d[1] = f2tf(v.y); d[2] = f2tf(v.z); d[3] = f2tf(v.w);
        }
        __syncthreads();
#pragma unroll
        for (int kk = 0; kk < BK; kk += 8) {
            uint32_t af[4][4];
#pragma unroll
            for (int mi = 0; mi < 4; mi++) {
                int r = wm + mi * 16 + gr;
                af[mi][0] = As[r * AS_LD + kk + tg];
                af[mi][1] = As[(r + 8) * AS_LD + kk + tg];
                af[mi][2] = As[r * AS_LD + kk + tg + 4];
                af[mi][3] = As[(r + 8) * AS_LD + kk + tg + 4];
            }
#pragma unroll
            for (int ni = 0; ni < 2; ni++) {
                int n = wn + ni * 8 + gr;
                uint32_t b0 = Bs[(kk + tg) * BS_LD + n];
                uint32_t b1 = Bs[(kk + tg + 4) * BS_LD + n];
#pragma unroll
                for (int mi = 0; mi < 4; mi++)
                    mma_tf32(acc[mi][ni], af[mi][0], af[mi][1], af[mi][2], af[mi][3], b0, b1);
            }
        }
        __syncthreads();
    }
#pragma unroll
    for (int mi = 0; mi < 4; mi++)
#pragma unroll
        for (int ni = 0; ni < 2; ni++) {
            int ra = row0 + wm + mi * 16 + gr;
            int ca = n0 + wn + ni * 8 + 2 * tg;
            float* a = acc[mi][ni];
            *(float2*)&g_outs[(size_t)ra * DD + ca] = make_float2(a[0], a[1]);
            *(float2*)&g_outs[(size_t)(ra + 8) * DD + ca] = make_float2(a[2], a[3]);
        }
}

// ---- weighted combine ----
__global__ void combine_kernel(float* __restrict__ out) {
    int idx = blockIdx.x * 256 + threadIdx.x;   // over NTOK*DD/4
    int t = idx / (DD / 4);
    int c = idx % (DD / 4);
    int p0 = g_pair_row[2 * t], p1 = g_pair_row[2 * t + 1];
    float wa = g_tk_w[2 * t], wb = g_tk_w[2 * t + 1];
    float4 a = *((const float4*)(g_outs + (size_t)p0 * DD) + c);
    float4 b = *((const float4*)(g_outs + (size_t)p1 * DD) + c);
    float4 r;
    r.x = wa * a.x + wb * b.x;
    r.y = wa * a.y + wb * b.y;
    r.z = wa * a.z + wb * b.z;
    r.w = wa * a.w + wb * b.w;
    ((float4*)out)[idx] = r;
}

extern "C" void kernel_launch(void* const* d_in, const int* in_sizes, int n_in,
                              void* d_out, int out_size) {
    const float* x  = (const float*)d_in[0];
    const float* gw = (const float*)d_in[1];
    const float* w1 = (const float*)d_in[2];
    const float* w2 = (const float*)d_in[3];
    const float* w3 = (const float*)d_in[4];
    float* out = (float*)d_out;

    init_kernel<<<(PADROWS + 255) / 256, 256>>>();
    router_kernel<<<NTOK, 256>>>(x, gw);
    scan_kernel<<<1, 32>>>();
    scatter_kernel<<<NPAIR / 256, 256>>>();
    gemm13_kernel<<<dim3(MM / BN, MAXTILES), 256>>>(x, w1, w3);
    gemm2_kernel<<<dim3(DD / BN, MAXTILES), 256>>>(w2);
    combine_kernel<<<(NTOK * DD / 4) / 256, 256>>>(out);
}

// round 2
// speedup vs baseline: 1.4058x; 1.4058x over previous
#include <cuda_runtime.h>
#include <cstdint>

#define NE 8
#define DD 2048
#define MM 7168
#define NTOK 4096
#define NPAIR 8192
#define PADROWS 9216
#define MAXTILES 72
#define BM 128
#define BN 64
#define BK 16
#define NS 3
#define AS_LD 20
#define BS_LD 72

// ---- scratch (device globals; no runtime allocation allowed) ----
__device__ float g_h[(size_t)PADROWS * MM];       // hidden after silu*w3 gate (tf32-rounded)
__device__ float g_outs[(size_t)PADROWS * DD];    // per-pair expert outputs (sorted order)
__device__ int   g_row_token[PADROWS];
__device__ int   g_pair_row[NPAIR];
__device__ int   g_tk_idx[NTOK * 2];
__device__ float g_tk_w[NTOK * 2];
__device__ int   g_counts[NE];
__device__ int   g_cursor[NE];
__device__ int   g_pad_off[NE + 1];
__device__ int   g_tile_expert[MAXTILES];
__device__ int   g_tile_row[MAXTILES];

// ---- helpers ----
__device__ __forceinline__ uint32_t f2tf(float f) {
    uint32_t u;
    asm("cvt.rna.tf32.f32 %0, %1;" : "=r"(u) : "f"(f));
    return u;
}

__device__ __forceinline__ void cp16(void* smem_dst, const void* gmem_src) {
    uint32_t s = (uint32_t)__cvta_generic_to_shared(smem_dst);
    asm volatile("cp.async.cg.shared.global [%0], [%1], 16;\n" :: "r"(s), "l"(gmem_src));
}
#define CP_COMMIT() asm volatile("cp.async.commit_group;\n" ::: "memory")
#define CP_WAIT(N)  asm volatile("cp.async.wait_group %0;\n" :: "n"(N) : "memory")

__device__ __forceinline__ void mma_tf32(float c[4],
                                         uint32_t a0, uint32_t a1, uint32_t a2, uint32_t a3,
                                         uint32_t b0, uint32_t b1) {
    asm volatile(
        "mma.sync.aligned.m16n8k8.row.col.f32.tf32.tf32.f32 "
        "{%0,%1,%2,%3},{%4,%5,%6,%7},{%8,%9},{%0,%1,%2,%3};\n"
        : "+f"(c[0]), "+f"(c[1]), "+f"(c[2]), "+f"(c[3])
        : "r"(a0), "r"(a1), "r"(a2), "r"(a3), "r"(b0), "r"(b1));
}

__device__ __forceinline__ float silu_f(float v) {
    return v / (1.0f + __expf(-v));
}

// ---- init ----
__global__ void init_kernel() {
    int i = blockIdx.x * 256 + threadIdx.x;
    if (i < PADROWS) g_row_token[i] = 0;
    if (i < NE) { g_counts[i] = 0; g_cursor[i] = 0; }
}

// ---- router: one block per token ----
__global__ __launch_bounds__(256) void router_kernel(const float* __restrict__ x,
                                                     const float* __restrict__ gw) {
    int t = blockIdx.x;
    const float* xr = x + (size_t)t * DD;
    float acc[NE];
#pragma unroll
    for (int e = 0; e < NE; e++) acc[e] = 0.0f;
    for (int k = threadIdx.x; k < DD; k += 256) {
        float xv = xr[k];
        float4 g0 = *(const float4*)(gw + (size_t)k * NE);
        float4 g1 = *(const float4*)(gw + (size_t)k * NE + 4);
        acc[0] += xv * g0.x; acc[1] += xv * g0.y;
        acc[2] += xv * g0.z; acc[3] += xv * g0.w;
        acc[4] += xv * g1.x; acc[5] += xv * g1.y;
        acc[6] += xv * g1.z; acc[7] += xv * g1.w;
    }
#pragma unroll
    for (int e = 0; e < NE; e++)
#pragma unroll
        for (int o = 16; o > 0; o >>= 1)
            acc[e] += __shfl_down_sync(0xffffffffu, acc[e], o);
    __shared__ float s[8][NE];
    int warp = threadIdx.x >> 5, lane = threadIdx.x & 31;
    if (lane == 0)
#pragma unroll
        for (int e = 0; e < NE; e++) s[warp][e] = acc[e];
    __syncthreads();
    if (threadIdx.x == 0) {
        float lg[NE];
#pragma unroll
        for (int e = 0; e < NE; e++) {
            float v = 0.0f;
#pragma unroll
            for (int w = 0; w < 8; w++) v += s[w][e];
            lg[e] = v;
        }
        float mx = lg[0];
#pragma unroll
        for (int e = 1; e < NE; e++) mx = fmaxf(mx, lg[e]);
        float p[NE];
#pragma unroll
        for (int e = 0; e < NE; e++) p[e] = expf(lg[e] - mx);
        int i1 = 0;
#pragma unroll
        for (int e = 1; e < NE; e++) if (p[e] > p[i1]) i1 = e;
        int i2 = -1;
#pragma unroll
        for (int e = 0; e < NE; e++)
            if (e != i1 && (i2 < 0 || p[e] > p[i2])) i2 = e;
        float denom = p[i1] + p[i2];
        g_tk_idx[2 * t] = i1; g_tk_idx[2 * t + 1] = i2;
        g_tk_w[2 * t] = p[i1] / denom;
        g_tk_w[2 * t + 1] = p[i2] / denom;
        atomicAdd(&g_counts[i1], 1);
        atomicAdd(&g_counts[i2], 1);
    }
}

// ---- scan ----
__global__ void scan_kernel() {
    if (blockIdx.x == 0 && threadIdx.x == 0) {
        int off = 0, tile = 0;
        for (int e = 0; e < NE; e++) {
            g_pad_off[e] = off;
            int c = g_counts[e];
            int nt = (c + BM - 1) >> 7;
            for (int i = 0; i < nt; i++) {
                g_tile_expert[tile] = e;
                g_tile_row[tile] = off + (i << 7);
                tile++;
            }
            off += nt << 7;
        }
        g_pad_off[NE] = off;
        for (; tile < MAXTILES; tile++) g_tile_expert[tile] = -1;
    }
}

// ---- scatter ----
__global__ void scatter_kernel() {
    int r = blockIdx.x * 256 + threadIdx.x;
    if (r >= NPAIR) return;
    int e = g_tk_idx[r];
    int p = g_pad_off[e] + atomicAdd(&g_cursor[e], 1);
    g_row_token[p] = r >> 1;
    g_pair_row[r] = p;
}

// ---- fused GEMM1/GEMM3 + silu gate, 3-stage cp.async pipeline ----
__global__ __launch_bounds__(256) void gemm13_kernel(const float* __restrict__ x,
                                                     const float* __restrict__ w1,
                                                     const float* __restrict__ w3) {
    extern __shared__ float sm[];
    float* Asb = sm;                                  // NS*BM*AS_LD
    float* B1b = Asb + NS * BM * AS_LD;               // NS*BK*BS_LD
    float* B3b = B1b + NS * BK * BS_LD;               // NS*BK*BS_LD
    int*   toks = (int*)(B3b + NS * BK * BS_LD);      // BM

    int e = g_tile_expert[blockIdx.y];
    if (e < 0) return;
    int row0 = g_tile_row[blockIdx.y];
    int n0 = blockIdx.x * BN;
    int tid = threadIdx.x;
    if (tid < BM) toks[tid] = g_row_token[row0 + tid];
    const float* W1 = w1 + (size_t)e * DD * MM + n0;
    const float* W3 = w3 + (size_t)e * DD * MM + n0;
    __syncthreads();

    int warp = tid >> 5, lane = tid & 31;
    int wm = (warp & 1) * 64, wn = (warp >> 1) * 16;
    int gr = lane >> 2, tg = lane & 3;

    float acc1[4][2][4], acc3[4][2][4];
#pragma unroll
    for (int mi = 0; mi < 4; mi++)
#pragma unroll
        for (int ni = 0; ni < 2; ni++)
#pragma unroll
            for (int j = 0; j < 4; j++) { acc1[mi][ni][j] = 0.f; acc3[mi][ni][j] = 0.f; }

    auto load_stage = [&](int s, int ki, bool pred) {
        if (pred) {
            float* A  = Asb + s * BM * AS_LD;
            float* B1 = B1b + s * BK * BS_LD;
            float* B3 = B3b + s * BK * BS_LD;
            int k0 = ki * BK;
#pragma unroll
            for (int i = 0; i < 2; i++) {
                int q = tid + i * 256;
                int row = q >> 2, c4 = q & 3;
                cp16(A + row * AS_LD + c4 * 4,
                     x + (size_t)toks[row] * DD + k0 + c4 * 4);
            }
            int row = tid >> 4, c4 = tid & 15;
            size_t go = (size_t)(k0 + row) * MM + c4 * 4;
            cp16(B1 + row * BS_LD + c4 * 4, W1 + go);
            cp16(B3 + row * BS_LD + c4 * 4, W3 + go);
        }
    };

    const int KIT = DD / BK;   // 128
#pragma unroll
    for (int s = 0; s < NS - 1; s++) { load_stage(s, s, true); CP_COMMIT(); }

    for (int i = 0; i < KIT; i++) {
        CP_WAIT(NS - 2);
        __syncthreads();
        int ls = i + NS - 1;
        load_stage(ls % NS, ls, ls < KIT);
        CP_COMMIT();

        const float* A  = Asb + (i % NS) * BM * AS_LD;
        const float* B1 = B1b + (i % NS) * BK * BS_LD;
        const float* B3 = B3b + (i % NS) * BK * BS_LD;
#pragma unroll
        for (int kk = 0; kk < BK; kk += 8) {
            uint32_t af[4][4];
#pragma unroll
            for (int mi = 0; mi < 4; mi++) {
                int r = wm + mi * 16 + gr;
                af[mi][0] = f2tf(A[r * AS_LD + kk + tg]);
                af[mi][1] = f2tf(A[(r + 8) * AS_LD + kk + tg]);
                af[mi][2] = f2tf(A[r * AS_LD + kk + tg + 4]);
                af[mi][3] = f2tf(A[(r + 8) * AS_LD + kk + tg + 4]);
            }
#pragma unroll
            for (int ni = 0; ni < 2; ni++) {
                int n = wn + ni * 8 + gr;
                uint32_t b10 = f2tf(B1[(kk + tg) * BS_LD + n]);
                uint32_t b11 = f2tf(B1[(kk + tg + 4) * BS_LD + n]);
                uint32_t b30 = f2tf(B3[(kk + tg) * BS_LD + n]);
                uint32_t b31 = f2tf(B3[(kk + tg + 4) * BS_LD + n]);
#pragma unroll
                for (int mi = 0; mi < 4; mi++) {
                    mma_tf32(acc1[mi][ni], af[mi][0], af[mi][1], af[mi][2], af[mi][3], b10, b11);
                    mma_tf32(acc3[mi][ni], af[mi][0], af[mi][1], af[mi][2], af[mi][3], b30, b31);
                }
            }
        }
    }

    // epilogue: silu(h1)*h3, stored pre-rounded to tf32 so gemm2 skips cvt
#pragma unroll
    for (int mi = 0; mi < 4; mi++)
#pragma unroll
        for (int ni = 0; ni < 2; ni++) {
            int ra = row0 + wm + mi * 16 + gr;
            int ca = n0 + wn + ni * 8 + 2 * tg;
            float* a1 = acc1[mi][ni];
            float* a3 = acc3[mi][ni];
            float2 lo, hi;
            lo.x = __uint_as_float(f2tf(silu_f(a1[0]) * a3[0]));
            lo.y = __uint_as_float(f2tf(silu_f(a1[1]) * a3[1]));
            hi.x = __uint_as_float(f2tf(silu_f(a1[2]) * a3[2]));
            hi.y = __uint_as_float(f2tf(silu_f(a1[3]) * a3[3]));
            *(float2*)&g_h[(size_t)ra * MM + ca] = lo;
            *(float2*)&g_h[(size_t)(ra + 8) * MM + ca] = hi;
        }
}

// ---- GEMM2: out_sorted = h @ w2, 3-stage cp.async pipeline ----
__global__ __launch_bounds__(256) void gemm2_kernel(const float* __restrict__ w2) {
    extern __shared__ float sm[];
    float* Asb = sm;                                  // NS*BM*AS_LD
    float* Bsb = Asb + NS * BM * AS_LD;               // NS*BK*BS_LD

    int e = g_tile_expert[blockIdx.y];
    if (e < 0) return;
    int row0 = g_tile_row[blockIdx.y];
    int n0 = blockIdx.x * BN;
    int tid = threadIdx.x;
    const float* W2 = w2 + (size_t)e * MM * DD + n0;

    int warp = tid >> 5, lane = tid & 31;
    int wm = (warp & 1) * 64, wn = (warp >> 1) * 16;
    int gr = lane >> 2, tg = lane & 3;

    float acc[4][2][4];
#pragma unroll
    for (int mi = 0; mi < 4; mi++)
#pragma unroll
        for (int ni = 0; ni < 2; ni++)
#pragma unroll
            for (int j = 0; j < 4; j++) acc[mi][ni][j] = 0.f;

    auto load_stage = [&](int s, int ki, bool pred) {
        if (pred) {
            float* A = Asb + s * BM * AS_LD;
            float* B = Bsb + s * BK * BS_LD;
            int k0 = ki * BK;
#pragma unroll
            for (int i = 0; i < 2; i++) {
                int q = tid + i * 256;
                int row = q >> 2, c4 = q & 3;
                cp16(A + row * AS_LD + c4 * 4,
                     g_h + (size_t)(row0 + row) * MM + k0 + c4 * 4);
            }
            int row = tid >> 4, c4 = tid & 15;
            cp16(B + row * BS_LD + c4 * 4, W2 + (size_t)(k0 + row) * DD + c4 * 4);
        }
    };

    const int KIT = MM / BK;   // 448
#pragma unroll
    for (int s = 0; s < NS - 1; s++) { load_stage(s, s, true); CP_COMMIT(); }

    for (int i = 0; i < KIT; i++) {
        CP_WAIT(NS - 2);
        __syncthreads();
        int ls = i + NS - 1;
        load_stage(ls % NS, ls, ls < KIT);
        CP_COMMIT();

        const float* A = Asb + (i % NS) * BM * AS_LD;
        const float* B = Bsb + (i % NS) * BK * BS_LD;
#pragma unroll
        for (int kk = 0; kk < BK; kk += 8) {
            uint32_t af[4][4];
#pragma unroll
            for (int mi = 0; mi < 4; mi++) {
                int r = wm + mi * 16 + gr;
                // g_h already tf32-rounded: reinterpret, no cvt
                af[mi][0] = __float_as_uint(A[r * AS_LD + kk + tg]);
                af[mi][1] = __float_as_uint(A[(r + 8) * AS_LD + kk + tg]);
                af[mi][2] = __float_as_uint(A[r * AS_LD + kk + tg + 4]);
                af[mi][3] = __float_as_uint(A[(r + 8) * AS_LD + kk + tg + 4]);
            }
#pragma unroll
            for (int ni = 0; ni < 2; ni++) {
                int n = wn + ni * 8 + gr;
                uint32_t b0 = f2tf(B[(kk + tg) * BS_LD + n]);
                uint32_t b1 = f2tf(B[(kk + tg + 4) * BS_LD + n]);
#pragma unroll
                for (int mi = 0; mi < 4; mi++)
                    mma_tf32(acc[mi][ni], af[mi][0], af[mi][1], af[mi][2], af[mi][3], b0, b1);
            }
        }
    }
#pragma unroll
    for (int mi = 0; mi < 4; mi++)
#pragma unroll
        for (int ni = 0; ni < 2; ni++) {
            int ra = row0 + wm + mi * 16 + gr;
            int ca = n0 + wn + ni * 8 + 2 * tg;
            float* a = acc[mi][ni];
            *(float2*)&g_outs[(size_t)ra * DD + ca] = make_float2(a[0], a[1]);
            *(float2*)&g_outs[(size_t)(ra + 8) * DD + ca] = make_float2(a[2], a[3]);
        }
}

// ---- weighted combine ----
__global__ void combine_kernel(float* __restrict__ out) {
    int idx = blockIdx.x * 256 + threadIdx.x;   // over NTOK*DD/4
    int t = idx / (DD / 4);
    int c = idx % (DD / 4);
    int p0 = g_pair_row[2 * t], p1 = g_pair_row[2 * t + 1];
    float wa = g_tk_w[2 * t], wb = g_tk_w[2 * t + 1];
    float4 a = *((const float4*)(g_outs + (size_t)p0 * DD) + c);
    float4 b = *((const float4*)(g_outs + (size_t)p1 * DD) + c);
    float4 r;
    r.x = wa * a.x + wb * b.x;
    r.y = wa * a.y + wb * b.y;
    r.z = wa * a.z + wb * b.z;
    r.w = wa * a.w + wb * b.w;
    ((float4*)out)[idx] = r;
}

extern "C" void kernel_launch(void* const* d_in, const int* in_sizes, int n_in,
                              void* d_out, int out_size) {
    const float* x  = (const float*)d_in[0];
    const float* gw = (const float*)d_in[1];
    const float* w1 = (const float*)d_in[2];
    const float* w2 = (const float*)d_in[3];
    const float* w3 = (const float*)d_in[4];
    float* out = (float*)d_out;

    const int smem13 = (NS * BM * AS_LD + 2 * NS * BK * BS_LD) * 4 + BM * 4;
    const int smem2  = (NS * BM * AS_LD + NS * BK * BS_LD) * 4;
    cudaFuncSetAttribute(gemm13_kernel, cudaFuncAttributeMaxDynamicSharedMemorySize, smem13);
    cudaFuncSetAttribute(gemm2_kernel,  cudaFuncAttributeMaxDynamicSharedMemorySize, smem2);

    init_kernel<<<(PADROWS + 255) / 256, 256>>>();
    router_kernel<<<NTOK, 256>>>(x, gw);
    scan_kernel<<<1, 32>>>();
    scatter_kernel<<<NPAIR / 256, 256>>>();
    gemm13_kernel<<<dim3(MM / BN, MAXTILES), 256, smem13>>>(x, w1, w3);
    gemm2_kernel<<<dim3(DD / BN, MAXTILES), 256, smem2>>>(w2);
    combine_kernel<<<(NTOK * DD / 4) / 256, 256>>>(out);
}